// round 11
// baseline (speedup 1.0000x reference)
#include <cuda_runtime.h>
#include <cuda_bf16.h>
#include <cstdint>

#define BB 16
#define CC 64
#define HH 192
#define WWID 192
#define HWSZ (HH * WWID)            // 36864
#define NSTEPS (BB * 128 * 512)     // 1,048,576 path steps
#define TPX 128                     // pixels per tile (MMA M)
#define NTILES (BB * (HWSZ / TPX))  // 4608
#define NCTAS (148 * 3)             // persistent grid, all co-resident
#define NTHREADS (NCTAS * 128)

__device__ unsigned char g_occ[BB * HWSZ];
__device__ int g_idx_is64 = 1;      // probe only ever ANDs this to 0 (int32 case)
__device__ unsigned g_count;        // barrier arrivals (self-resets)
__device__ unsigned g_sense;        // barrier generation (monotonic across replays)

// ---------------------------------------------------------------------------
__device__ __forceinline__ uint32_t smem_u32(const void* p) {
    uint32_t a;
    asm("{ .reg .u64 t; cvta.to.shared.u64 t, %1; cvt.u32.u64 %0, t; }"
        : "=r"(a) : "l"(p));
    return a;
}
#define SWZ(o) ((uint32_t)(o) ^ ((((uint32_t)(o)) >> 3) & 0x70))

#define LDSM4(R, ADDR)                                                        \
    asm volatile("ldmatrix.sync.aligned.m8n8.x4.shared.b16 {%0,%1,%2,%3}, [%4];" \
                 : "=r"((R)[0]), "=r"((R)[1]), "=r"((R)[2]), "=r"((R)[3])     \
                 : "r"(ADDR))

#define MMA16816(C, A, B0, B1)                                                \
    asm volatile("mma.sync.aligned.m16n8k16.row.col.f32.bf16.bf16.f32 "       \
                 "{%0,%1,%2,%3}, {%4,%5,%6,%7}, {%8,%9}, {%0,%1,%2,%3};"      \
                 : "+f"((C)[0]), "+f"((C)[1]), "+f"((C)[2]), "+f"((C)[3])     \
                 : "r"((A)[0]), "r"((A)[1]), "r"((A)[2]), "r"((A)[3]),        \
                   "r"(B0), "r"(B1))

// Sense-reversal grid barrier. Safe: all NCTAS CTAs are co-resident (grid ==
// max resident occupancy), so every CTA is guaranteed to arrive.
// g_count self-resets; g_sense grows monotonically (snapshot-relative waits),
// so the state is replay-safe under CUDA-graph capture.
__device__ __forceinline__ void grid_bar(unsigned sense0, unsigned ph) {
    __threadfence();                 // publish this thread's prior writes
    __syncthreads();
    if (threadIdx.x == 0) {
        unsigned arrived = atomicAdd(&g_count, 1u);
        if (arrived == NCTAS - 1) {
            g_count = 0;             // last arrival resets for next barrier
            __threadfence();
            atomicAdd(&g_sense, 1u); // release
        } else {
            while ((int)(*(volatile unsigned*)&g_sense - (sense0 + ph)) < 0) {}
        }
        __threadfence();             // acquire
    }
    __syncthreads();
}

__device__ __forceinline__ unsigned ldcg_u8(const unsigned char* p) {
    unsigned v;
    asm volatile("ld.global.cg.u8 %0, [%1];" : "=r"(v) : "l"(p));
    return v;
}

// ---------------------------------------------------------------------------
// ONE persistent kernel:
//  phase 0: zero g_occ + probe path_idx dtype        -> grid barrier
//  phase 1: mark occupancy from path_idx             -> grid barrier
//  phase 2: per-tile masked GEMM (R10 core): register-batched LDG staging of
//           A (f32 -> bf16 hi/lo split, transposed), mma.sync 3-pass
//           (hi*hi + hi*lo + lo*hi), masked epilogue. B = W^T staged once.
// ---------------------------------------------------------------------------
__global__ void __launch_bounds__(128, 3)
fused_kernel(const float* __restrict__ feat,
             const void*  __restrict__ pidx,    // int32 or int64
             const float* __restrict__ Wm,      // [64][64] (k, c)
             const float* __restrict__ bm,      // [64]
             float* __restrict__ out) {
    __shared__ __align__(1024) unsigned char sAhi[TPX * 128];  // 16 KB
    __shared__ __align__(1024) unsigned char sAlo[TPX * 128];  // 16 KB
    __shared__ __align__(1024) unsigned char sBhi[64 * 128];   // 8 KB
    __shared__ __align__(1024) unsigned char sBlo[64 * 128];   // 8 KB (48 KB)

    const int tid  = threadIdx.x;
    const int warp = tid >> 5;
    const int lane = tid & 31;
    const int gtid = blockIdx.x * 128 + tid;

    // Snapshot barrier generation BEFORE any arrival this launch.
    const unsigned sense0 = *(volatile unsigned*)&g_sense;

    // ---- Phase 0: zero occupancy flags + dtype probe ----
    {
        uint4* p = reinterpret_cast<uint4*>(g_occ);
        for (int i = gtid; i < (BB * HWSZ) / 16; i += NTHREADS)
            p[i] = make_uint4(0u, 0u, 0u, 0u);
        if (gtid < 1024) {
            const int* words = (const int*)pidx;
            if (words[2 * gtid + 1] != 0) atomicAnd(&g_idx_is64, 0);
        }
    }

    // ---- Stage B = W^T split once (before barrier; W is launch-constant) ----
    for (int i = tid; i < 64 * 64; i += 128) {
        int n = i & 63;
        int k = i >> 6;
        float w = Wm[k * 64 + n];
        __nv_bfloat16 h = __float2bfloat16(w);
        __nv_bfloat16 l = __float2bfloat16(w - __bfloat162float(h));
        uint32_t off = SWZ((uint32_t)(n * 128 + k * 2));
        *reinterpret_cast<unsigned short*>(sBhi + off) = __bfloat16_as_ushort(h);
        *reinterpret_cast<unsigned short*>(sBlo + off) = __bfloat16_as_ushort(l);
    }

    grid_bar(sense0, 1);

    // ---- Phase 1: mark occupancy ----
    {
        const int is64 = *(volatile int*)&g_idx_is64;
        if (is64) {
            const long long* px64 = (const long long*)pidx;
            for (int i = gtid; i < NSTEPS; i += NTHREADS) {
                int b = i >> 16;
                int hw = (int)px64[i];
                if ((unsigned)hw < (unsigned)HWSZ) g_occ[b * HWSZ + hw] = 1;
            }
        } else {
            const int* px32 = (const int*)pidx;
            for (int i = gtid; i < NSTEPS; i += NTHREADS) {
                int b = i >> 16;
                int hw = px32[i];
                if ((unsigned)hw < (unsigned)HWSZ) g_occ[b * HWSZ + hw] = 1;
            }
        }
    }

    grid_bar(sense0, 2);

    // ---- Phase 2: persistent tile loop (R10 GEMM core) ----
    const int g = lane >> 2, t = lane & 3;
    const int px = warp * 32;
    const uint32_t mask   = (uint32_t)(lane & 7) << 4;
    const uint32_t aRow   = (uint32_t)(px + (lane & 15)) * 128;
    const uint32_t aChunk = (uint32_t)(lane & 16);
    const uint32_t bRow   = (uint32_t)((lane & 7) + ((lane & 16) >> 1)) * 128;
    const uint32_t bChunk = (uint32_t)((lane & 8) << 1);
    const uint32_t aHi = smem_u32(sAhi);
    const uint32_t aLo = smem_u32(sAlo);
    const uint32_t aBases[3] = { aHi, aHi, aLo };
    const uint32_t bBases[3] = { smem_u32(sBhi), smem_u32(sBlo), smem_u32(sBhi) };

    float bias0[8], bias1[8];
    #pragma unroll
    for (int n = 0; n < 8; n++) {
        bias0[n] = __ldg(&bm[n * 8 + 2 * t]);
        bias1[n] = __ldg(&bm[n * 8 + 2 * t + 1]);
    }

    for (int tile = blockIdx.x; tile < NTILES; tile += NCTAS) {
        const int b   = tile / (HWSZ / TPX);
        const int hw0 = (tile - b * (HWSZ / TPX)) * TPX;

        // Stage A: thread = pixel; 64 batched strided LDGs, convert, STS.128
        {
            const float* fbase = feat + (size_t)b * CC * HWSZ + hw0 + tid;
            const uint32_t arow = (uint32_t)tid * 128;
            #pragma unroll
            for (int c = 0; c < 8; c++) {
                uint32_t hp[4], lp[4];
                #pragma unroll
                for (int j = 0; j < 4; j++) {
                    int k0 = c * 8 + 2 * j;
                    float a0 = fbase[(size_t)k0 * HWSZ];
                    float a1 = fbase[(size_t)(k0 + 1) * HWSZ];
                    __nv_bfloat16 h0 = __float2bfloat16(a0);
                    __nv_bfloat16 h1 = __float2bfloat16(a1);
                    __nv_bfloat16 l0 = __float2bfloat16(a0 - __bfloat162float(h0));
                    __nv_bfloat16 l1 = __float2bfloat16(a1 - __bfloat162float(h1));
                    hp[j] = (uint32_t)__bfloat16_as_ushort(h0) |
                            ((uint32_t)__bfloat16_as_ushort(h1) << 16);
                    lp[j] = (uint32_t)__bfloat16_as_ushort(l0) |
                            ((uint32_t)__bfloat16_as_ushort(l1) << 16);
                }
                uint32_t off = SWZ(arow + c * 16);
                asm volatile("st.shared.v4.b32 [%0], {%1, %2, %3, %4};"
                             :: "r"(aHi + off),
                                "r"(hp[0]), "r"(hp[1]), "r"(hp[2]), "r"(hp[3]) : "memory");
                asm volatile("st.shared.v4.b32 [%0], {%1, %2, %3, %4};"
                             :: "r"(aLo + off),
                                "r"(lp[0]), "r"(lp[1]), "r"(lp[2]), "r"(lp[3]) : "memory");
            }
        }
        __syncthreads();

        // MMA: 3 split passes x 4 K-steps
        float c_[2][8][4];
        #pragma unroll
        for (int m = 0; m < 2; m++)
            #pragma unroll
            for (int n = 0; n < 8; n++)
                #pragma unroll
                for (int r = 0; r < 4; r++) c_[m][n][r] = 0.0f;

        #pragma unroll
        for (int ps = 0; ps < 3; ps++) {
            const uint32_t aB = aBases[ps] + aRow;
            const uint32_t bB = bBases[ps] + bRow;
            #pragma unroll
            for (int k = 0; k < 4; k++) {
                const uint32_t ac = (aChunk + (uint32_t)k * 32) ^ mask;  // no carry
                const uint32_t bc = (bChunk + (uint32_t)k * 32) ^ mask;
                uint32_t a0[4], a1[4];
                LDSM4(a0, aB + ac);
                LDSM4(a1, aB + 2048 + ac);
                uint32_t bf[8][2];
                #pragma unroll
                for (int np = 0; np < 4; np++) {
                    uint32_t r4[4];
                    LDSM4(r4, bB + (uint32_t)np * 2048 + bc);
                    bf[2 * np][0] = r4[0]; bf[2 * np][1] = r4[1];
                    bf[2 * np + 1][0] = r4[2]; bf[2 * np + 1][1] = r4[3];
                }
                #pragma unroll
                for (int n = 0; n < 8; n++) {
                    MMA16816(c_[0][n], a0, bf[n][0], bf[n][1]);
                    MMA16816(c_[1][n], a1, bf[n][0], bf[n][1]);
                }
            }
        }

        // Epilogue: mask (L2-coherent loads) + bias; full-sector stores
        const unsigned char* occp = g_occ + b * HWSZ + hw0 + px + g;
        float msk[4];
        msk[0] = ldcg_u8(occp)      ? 1.0f : 0.0f;
        msk[1] = ldcg_u8(occp + 8)  ? 1.0f : 0.0f;
        msk[2] = ldcg_u8(occp + 16) ? 1.0f : 0.0f;
        msk[3] = ldcg_u8(occp + 24) ? 1.0f : 0.0f;

        float* ob = out + (size_t)b * CC * HWSZ;
        #pragma unroll
        for (int m = 0; m < 2; m++) {
            const int hwA = hw0 + px + m * 16 + g;
            const int hwB = hwA + 8;
            const float mA = msk[2 * m], mB = msk[2 * m + 1];
            #pragma unroll
            for (int n = 0; n < 8; n++) {
                const size_t ch = (size_t)(n * 8 + 2 * t);
                ob[ch * HWSZ + hwA]       = (c_[m][n][0] + bias0[n]) * mA;
                ob[(ch + 1) * HWSZ + hwA] = (c_[m][n][1] + bias1[n]) * mA;
                ob[ch * HWSZ + hwB]       = (c_[m][n][2] + bias0[n]) * mB;
                ob[(ch + 1) * HWSZ + hwB] = (c_[m][n][3] + bias1[n]) * mB;
            }
        }
        __syncthreads();   // all warps done reading sA before next staging
    }
}

// ---------------------------------------------------------------------------
extern "C" void kernel_launch(void* const* d_in, const int* in_sizes, int n_in,
                              void* d_out, int out_size) {
    const float* feat = (const float*)d_in[0];      // [B, C, H, W] f32
    const void*  pidx = d_in[1];                    // [B, P, L] int32 or int64
    const float* Wm   = (const float*)d_in[2];      // [C, C] f32
    const float* bm   = (const float*)d_in[3];      // [C] f32
    float*       out  = (float*)d_out;              // [B, C, H, W] f32

    (void)in_sizes; (void)n_in; (void)out_size;

    fused_kernel<<<NCTAS, 128>>>(feat, pidx, Wm, bm, out);
}